// round 7
// baseline (speedup 1.0000x reference)
#include <cuda_runtime.h>
#include <cuda_bf16.h>
#include <math.h>
#include <stdint.h>

// Problem dims
#define NTOK 16384      // B*S
#define DIM  4096       // D (K of both GEMMs)
#define HID  2048       // H (N of GEMM1)
#define NEXP 64
#define TOPK 3

// Output layout (float32, concatenated flattened reference outputs)
#define OFF_W 0
#define OFF_I (NTOK * TOPK)
#define OFF_M (2 * NTOK * TOPK)
#define OFF_K (2 * NTOK * TOPK + NTOK * NEXP)

// Scratch (device globals)
#define XPLANE ((size_t)NTOK * DIM)
#define WPLANE ((size_t)HID * DIM)
#define FLAG_CAP 2048
__device__ __align__(16) __nv_bfloat16 g_xs[2 * XPLANE];   // 268 MB: x 2-way splits
__device__ __align__(16) __nv_bfloat16 g_w1t[2 * WPLANE];  // 33 MB: W1^T 2-way splits [N][K]
__device__ float g_h[(size_t)NTOK * HID];                  // 134 MB
__device__ float g_logits[(size_t)NTOK * NEXP];            // 4 MB
__device__ int   g_kdyn[NTOK];
__device__ int   g_nflag;
__device__ int   g_flaglist[FLAG_CAP];

// ---------------------------------------------------------------------------
// PTX helpers (baseline sm_80+ ISA: ldmatrix / mma.sync / cp.async)
// ---------------------------------------------------------------------------
__device__ __forceinline__ uint32_t smem_u32(const void* p) {
    uint32_t a;
    asm("{ .reg .u64 t; cvta.to.shared.u64 t, %1; cvt.u32.u64 %0, t; }" : "=r"(a) : "l"(p));
    return a;
}
__device__ __forceinline__ void cp_async16(uint32_t dst, const void* src) {
    asm volatile("cp.async.cg.shared.global [%0], [%1], 16;" :: "r"(dst), "l"(src));
}
__device__ __forceinline__ void cp_commit() {
    asm volatile("cp.async.commit_group;");
}
template <int N>
__device__ __forceinline__ void cp_wait() {
    asm volatile("cp.async.wait_group %0;" :: "n"(N));
}
__device__ __forceinline__ void ldmatrix_x4(uint32_t& r0, uint32_t& r1, uint32_t& r2, uint32_t& r3,
                                            uint32_t addr) {
    asm volatile("ldmatrix.sync.aligned.m8n8.x4.shared.b16 {%0,%1,%2,%3}, [%4];"
                 : "=r"(r0), "=r"(r1), "=r"(r2), "=r"(r3) : "r"(addr));
}
__device__ __forceinline__ void mma_bf16(float* c, const uint32_t* a, const uint32_t* b) {
    asm volatile(
        "mma.sync.aligned.m16n8k16.row.col.f32.bf16.bf16.f32 "
        "{%0,%1,%2,%3}, {%4,%5,%6,%7}, {%8,%9}, {%0,%1,%2,%3};"
        : "+f"(c[0]), "+f"(c[1]), "+f"(c[2]), "+f"(c[3])
        : "r"(a[0]), "r"(a[1]), "r"(a[2]), "r"(a[3]), "r"(b[0]), "r"(b[1]));
}

// ---------------------------------------------------------------------------
// 2-way bf16 splits
// ---------------------------------------------------------------------------
__device__ __forceinline__ void split2(float v, __nv_bfloat16& a, __nv_bfloat16& b) {
    a = __float2bfloat16_rn(v);
    b = __float2bfloat16_rn(v - __bfloat162float(a));
}

__global__ __launch_bounds__(256) void split_x(const float* __restrict__ x) {
    size_t i = ((size_t)blockIdx.x * 256 + threadIdx.x) * 4;
    float4 v = *(const float4*)(x + i);
    __nv_bfloat16 a[4], b[4];
    split2(v.x, a[0], b[0]);
    split2(v.y, a[1], b[1]);
    split2(v.z, a[2], b[2]);
    split2(v.w, a[3], b[3]);
    ushort4 pa, pb;
    pa.x = __bfloat16_as_ushort(a[0]); pa.y = __bfloat16_as_ushort(a[1]);
    pa.z = __bfloat16_as_ushort(a[2]); pa.w = __bfloat16_as_ushort(a[3]);
    pb.x = __bfloat16_as_ushort(b[0]); pb.y = __bfloat16_as_ushort(b[1]);
    pb.z = __bfloat16_as_ushort(b[2]); pb.w = __bfloat16_as_ushort(b[3]);
    *(ushort4*)(g_xs + i)          = pa;
    *(ushort4*)(g_xs + XPLANE + i) = pb;
}

// W1 [K][N] fp32 -> W1^T [N][K] bf16 x2 (tiled transpose)
__global__ __launch_bounds__(256) void split_w1t(const float* __restrict__ W1) {
    __shared__ float t[32][33];
    const int k0 = blockIdx.x * 32;
    const int n0 = blockIdx.y * 32;
    const int tx = threadIdx.x;  // 0..31
    const int ty = threadIdx.y;  // 0..7
    #pragma unroll
    for (int j = 0; j < 4; j++)
        t[ty + 8 * j][tx] = W1[(size_t)(k0 + ty + 8 * j) * HID + n0 + tx];
    __syncthreads();
    #pragma unroll
    for (int j = 0; j < 4; j++) {
        const int n = n0 + ty + 8 * j;
        const int kk = k0 + tx;
        __nv_bfloat16 a, b;
        split2(t[tx][ty + 8 * j], a, b);
        g_w1t[(size_t)n * DIM + kk]          = a;
        g_w1t[WPLANE + (size_t)n * DIM + kk] = b;
    }
}

// ---------------------------------------------------------------------------
// GEMM1 via mma.sync bf16, 2-way split (3 passes into one fp32 accumulator):
//   h = relu(x1*w1 + x1*w2 + x2*w1 + b1)
// CTA 128x128, BK=32, 512 threads: 16 warps as 4x4, warp tile 32x32.
// 3-stage cp.async pipeline. SMEM pitch 40 bf16 (80B): ldmatrix conflict-free.
// ---------------------------------------------------------------------------
#define G1_BM 128
#define G1_BN 128
#define G1_BK 32
#define PITCH 40
#define TILE_B (128 * PITCH * 2)          // 10240 bytes per tile
#define STAGE_B (4 * TILE_B)              // A1,A2,B1,B2 = 40960
#define NSTAGE 3
#define G1_SMEM (NSTAGE * STAGE_B)        // 122880
#define G1_NIT (DIM / G1_BK)              // 128

__global__ __launch_bounds__(512, 1) void gemm1_hmma(const float* __restrict__ bias) {
    extern __shared__ char smem[];
    const uint32_t sbase = smem_u32(smem);

    const int tid  = threadIdx.x;
    const int warp = tid >> 5;
    const int lane = tid & 31;
    const int m0 = blockIdx.y * G1_BM;
    const int n0 = blockIdx.x * G1_BN;

    const int wm = (warp >> 2) * 32;   // warp M offset
    const int wn = (warp & 3) * 32;    // warp N offset

    // global load mapping: tile p = tid>>7 (A1,A2,B1,B2), row = tid&127, 4x16B
    const int lp = tid >> 7;
    const int lr = tid & 127;
    const __nv_bfloat16* lsrc =
        (lp < 2) ? (g_xs + (size_t)lp * XPLANE + (size_t)(m0 + lr) * DIM)
                 : (g_w1t + (size_t)(lp - 2) * WPLANE + (size_t)(n0 + lr) * DIM);
    const uint32_t ldst_off = lp * TILE_B + lr * (PITCH * 2);

    float acc[2][4][4];
    #pragma unroll
    for (int i = 0; i < 2; i++)
        #pragma unroll
        for (int j = 0; j < 4; j++)
            #pragma unroll
            for (int q = 0; q < 4; q++) acc[i][j][q] = 0.f;

    auto load_stage = [&](int stage, int k0) {
        const uint32_t dst = sbase + stage * STAGE_B + ldst_off;
        const __nv_bfloat16* src = lsrc + k0;
        #pragma unroll
        for (int c = 0; c < 4; c++)
            cp_async16(dst + c * 16, src + c * 8);
        cp_commit();
    };

    load_stage(0, 0);
    load_stage(1, G1_BK);

    const int g = lane >> 3, r = lane & 7;

    for (int it = 0; it < G1_NIT; it++) {
        if (it + 2 < G1_NIT) {
            load_stage((it + 2) % NSTAGE, (it + 2) * G1_BK);
            cp_wait<2>();
        } else {
            cp_wait<0>();
        }
        __syncthreads();

        const uint32_t sb = sbase + (it % NSTAGE) * STAGE_B;
        const uint32_t A1 = sb;
        const uint32_t A2 = sb + TILE_B;
        const uint32_t B1 = sb + 2 * TILE_B;
        const uint32_t B2 = sb + 3 * TILE_B;

        #pragma unroll
        for (int s = 0; s < 2; s++) {          // two k16 steps
            uint32_t a1f[2][4], a2f[2][4];
            #pragma unroll
            for (int mb = 0; mb < 2; mb++) {
                const uint32_t off =
                    (uint32_t)(wm + mb * 16 + (g & 1) * 8 + r) * (PITCH * 2) + s * 32 + (g >> 1) * 16;
                ldmatrix_x4(a1f[mb][0], a1f[mb][1], a1f[mb][2], a1f[mb][3], A1 + off);
                ldmatrix_x4(a2f[mb][0], a2f[mb][1], a2f[mb][2], a2f[mb][3], A2 + off);
            }
            uint32_t b1f[4][2], b2f[4][2];
            #pragma unroll
            for (int nbp = 0; nbp < 2; nbp++) {
                const uint32_t off =
                    (uint32_t)(wn + nbp * 16 + (g >> 1) * 8 + r) * (PITCH * 2) + s * 32 + (g & 1) * 16;
                uint32_t q0, q1, q2, q3;
                ldmatrix_x4(q0, q1, q2, q3, B1 + off);
                b1f[nbp * 2][0] = q0; b1f[nbp * 2][1] = q1;
                b1f[nbp * 2 + 1][0] = q2; b1f[nbp * 2 + 1][1] = q3;
                ldmatrix_x4(q0, q1, q2, q3, B2 + off);
                b2f[nbp * 2][0] = q0; b2f[nbp * 2][1] = q1;
                b2f[nbp * 2 + 1][0] = q2; b2f[nbp * 2 + 1][1] = q3;
            }
            #pragma unroll
            for (int mb = 0; mb < 2; mb++)
                #pragma unroll
                for (int nb = 0; nb < 4; nb++)
                    mma_bf16(acc[mb][nb], a1f[mb], b1f[nb]);
            #pragma unroll
            for (int mb = 0; mb < 2; mb++)
                #pragma unroll
                for (int nb = 0; nb < 4; nb++)
                    mma_bf16(acc[mb][nb], a1f[mb], b2f[nb]);
            #pragma unroll
            for (int mb = 0; mb < 2; mb++)
                #pragma unroll
                for (int nb = 0; nb < 4; nb++)
                    mma_bf16(acc[mb][nb], a2f[mb], b1f[nb]);
        }
        __syncthreads();
    }

    // epilogue: bias + relu
    const int crow = lane >> 2;
    const int ccol = (lane & 3) * 2;
    #pragma unroll
    for (int mb = 0; mb < 2; mb++) {
        #pragma unroll
        for (int nb = 0; nb < 4; nb++) {
            const int col = n0 + wn + nb * 8 + ccol;
            const float b0 = bias[col], b1v = bias[col + 1];
            const int row0 = m0 + wm + mb * 16 + crow;
            float2 v0, v1;
            v0.x = fmaxf(acc[mb][nb][0] + b0, 0.f);
            v0.y = fmaxf(acc[mb][nb][1] + b1v, 0.f);
            v1.x = fmaxf(acc[mb][nb][2] + b0, 0.f);
            v1.y = fmaxf(acc[mb][nb][3] + b1v, 0.f);
            *(float2*)(g_h + (size_t)row0 * HID + col)       = v0;
            *(float2*)(g_h + (size_t)(row0 + 8) * HID + col) = v1;
        }
    }
}

// ---------------------------------------------------------------------------
// GEMM2 (high accuracy): g_logits = x @ W, fp32 partials + fp64 flush (proven)
// ---------------------------------------------------------------------------
__global__ __launch_bounds__(256) void gemm_logits(
    const float* __restrict__ A, const float* __restrict__ B
) {
    const int K = DIM;
    __shared__ float As_t[32][64];
    __shared__ float Bs[32][64];

    const int tid = threadIdx.x;
    const int m0 = blockIdx.x * 64;
    const int tg4 = (tid >> 4) * 4;
    const int eg4 = (tid & 15) * 4;

    double acc[4][4];
    #pragma unroll
    for (int i = 0; i < 4; i++)
        #pragma unroll
        for (int j = 0; j < 4; j++) acc[i][j] = 0.0;

    const int ar = tid >> 3;
    const int ac = (tid & 7) * 4;

    for (int k0 = 0; k0 < K; k0 += 32) {
        __syncthreads();
        #pragma unroll
        for (int it = 0; it < 2; it++) {
            const int r = it * 32 + ar;
            float4 av = *(const float4*)(A + (size_t)(m0 + r) * K + k0 + ac);
            As_t[ac + 0][r] = av.x;
            As_t[ac + 1][r] = av.y;
            As_t[ac + 2][r] = av.z;
            As_t[ac + 3][r] = av.w;
        }
        #pragma unroll
        for (int it = 0; it < 2; it++) {
            const int f = tid * 2 + it;
            const int kk = f >> 4;
            const int e4 = (f & 15) * 4;
            *(float4*)&Bs[kk][e4] = *(const float4*)(B + (size_t)(k0 + kk) * NEXP + e4);
        }
        __syncthreads();

        float part[4][4];
        #pragma unroll
        for (int i = 0; i < 4; i++)
            #pragma unroll
            for (int j = 0; j < 4; j++) part[i][j] = 0.f;

        #pragma unroll
        for (int kk = 0; kk < 32; kk++) {
            float4 a = *(const float4*)&As_t[kk][tg4];
            float4 b = *(const float4*)&Bs[kk][eg4];
            float av[4] = {a.x, a.y, a.z, a.w};
            float bv[4] = {b.x, b.y, b.z, b.w};
            #pragma unroll
            for (int i = 0; i < 4; i++)
                #pragma unroll
                for (int j = 0; j < 4; j++)
                    part[i][j] = fmaf(av[i], bv[j], part[i][j]);
            if ((kk & 7) == 7) {
                #pragma unroll
                for (int i = 0; i < 4; i++)
                    #pragma unroll
                    for (int j = 0; j < 4; j++) {
                        acc[i][j] += (double)part[i][j];
                        part[i][j] = 0.f;
                    }
            }
        }
    }

    #pragma unroll
    for (int i = 0; i < 4; i++) {
        const int row = m0 + tg4 + i;
        #pragma unroll
        for (int j = 0; j < 4; j++)
            g_logits[(size_t)row * NEXP + eg4 + j] = (float)acc[i][j];
    }
}

// ---------------------------------------------------------------------------
__global__ void reset_flags() { g_nflag = 0; }

// ---------------------------------------------------------------------------
// predictor: z = h@W2 + b2 -> sigmoid -> dynamic_k; flag near-boundary tokens
// ---------------------------------------------------------------------------
#define ZB 1.6094379124341003f
#define ZEPS 1e-3f

__global__ __launch_bounds__(256) void predictor_k(
    const float* __restrict__ W2, const float* __restrict__ b2
) {
    __shared__ float red[256];
    const int n = blockIdx.x;
    const int tid = threadIdx.x;
    const float4* hp = (const float4*)(g_h + (size_t)n * HID);
    const float4* wp = (const float4*)W2;
    float acc = 0.f;
    #pragma unroll
    for (int j = tid; j < HID / 4; j += 256) {
        float4 h4 = hp[j];
        float4 w4 = wp[j];
        acc = fmaf(h4.x, w4.x, acc);
        acc = fmaf(h4.y, w4.y, acc);
        acc = fmaf(h4.z, w4.z, acc);
        acc = fmaf(h4.w, w4.w, acc);
    }
    red[tid] = acc;
    __syncthreads();
    for (int s = 128; s > 0; s >>= 1) {
        if (tid < s) red[tid] += red[tid + s];
        __syncthreads();
    }
    if (tid == 0) {
        float z = red[0] + b2[0];
        float score = 1.0f / (1.0f + expf(-z));
        float kf = rintf(score * 3.0f) + 1.0f;
        kf = fminf(fmaxf(kf, 1.0f), 3.0f);
        g_kdyn[n] = (int)kf;
        if (fabsf(z) < ZEPS || fabsf(z - ZB) < ZEPS || fabsf(z + ZB) < ZEPS) {
            int slot = atomicAdd(&g_nflag, 1);
            if (slot < FLAG_CAP) g_flaglist[slot] = n;
        }
    }
}

// ---------------------------------------------------------------------------
// repair: recompute z to ~fp64 accuracy for flagged tokens
// ---------------------------------------------------------------------------
__global__ __launch_bounds__(256) void repair_k(
    const float* __restrict__ x, const float* __restrict__ W1,
    const float* __restrict__ b1, const float* __restrict__ W2,
    const float* __restrict__ b2
) {
    __shared__ float xs[DIM];
    __shared__ double zred[256];
    const int tid = threadIdx.x;
    const int cnt = min(g_nflag, FLAG_CAP);

    for (int w = blockIdx.x; w < cnt; w += gridDim.x) {
        const int n = g_flaglist[w];
        for (int j = tid; j < DIM / 4; j += 256)
            *(float4*)&xs[j * 4] = *(const float4*)(x + (size_t)n * DIM + j * 4);
        __syncthreads();

        double zpart = 0.0;
        #pragma unroll
        for (int t = 0; t < HID / 256; t++) {
            const int j = tid + t * 256;
            double aj = 0.0;
            for (int kc = 0; kc < DIM; kc += 64) {
                float p = 0.f;
                #pragma unroll
                for (int k = 0; k < 64; k++)
                    p = fmaf(xs[kc + k], W1[(size_t)(kc + k) * HID + j], p);
                aj += (double)p;
            }
            float hj = fmaxf((float)(aj + (double)b1[j]), 0.f);
            zpart += (double)hj * (double)W2[j];
        }
        zred[tid] = zpart;
        __syncthreads();
        for (int s = 128; s > 0; s >>= 1) {
            if (tid < s) zred[tid] += zred[tid + s];
            __syncthreads();
        }
        if (tid == 0) {
            float z = (float)(zred[0] + (double)b2[0]);
            float score = 1.0f / (1.0f + expf(-z));
            float kf = rintf(score * 3.0f) + 1.0f;
            kf = fminf(fmaxf(kf, 1.0f), 3.0f);
            g_kdyn[n] = (int)kf;
        }
        __syncthreads();
    }
}

// ---------------------------------------------------------------------------
// finalize: softmax/top-3 (rounded probs, lower-index ties)/mask/renorm
// ---------------------------------------------------------------------------
__global__ __launch_bounds__(256) void finalize(float* __restrict__ out) {
    const int warp = threadIdx.x >> 5;
    const int lane = threadIdx.x & 31;
    const int n = blockIdx.x * 8 + warp;

    const float* lp = g_logits + (size_t)n * NEXP;
    float l0 = lp[lane];
    float l1 = lp[lane + 32];

    float m = fmaxf(l0, l1);
    #pragma unroll
    for (int o = 16; o > 0; o >>= 1) m = fmaxf(m, __shfl_xor_sync(0xFFFFFFFFu, m, o));
    float e0 = expf(l0 - m);
    float e1 = expf(l1 - m);
    float s = e0 + e1;
    #pragma unroll
    for (int o = 16; o > 0; o >>= 1) s += __shfl_xor_sync(0xFFFFFFFFu, s, o);

    float p0 = e0 / s;
    float p1 = e1 / s;

    float c0 = p0, c1 = p1;
    float tv[TOPK];
    int   ti[TOPK];
    #pragma unroll
    for (int r = 0; r < TOPK; r++) {
        float v;
        int idx;
        if (c1 > c0) { v = c1; idx = lane + 32; }
        else         { v = c0; idx = lane; }
        #pragma unroll
        for (int o = 16; o > 0; o >>= 1) {
            float ov = __shfl_xor_sync(0xFFFFFFFFu, v, o);
            int   oi = __shfl_xor_sync(0xFFFFFFFFu, idx, o);
            if (ov > v || (ov == v && oi < idx)) { v = ov; idx = oi; }
        }
        tv[r] = v;
        ti[r] = idx;
        if (idx == lane)      c0 = -1.0f;
        if (idx == lane + 32) c1 = -1.0f;
    }

    const int k = g_kdyn[n];

    float msum = 0.f;
    #pragma unroll
    for (int r = 0; r < TOPK; r++)
        if (r < k) msum += tv[r];
    const float denom = msum + 1e-8f;

    if (lane < TOPK) {
        float w = (lane < k ? tv[lane] : 0.f) / denom;
        out[OFF_W + (size_t)n * TOPK + lane] = w;
        out[OFF_I + (size_t)n * TOPK + lane] = (float)ti[lane];
    }

    float m0v = 0.f, m1v = 0.f;
    #pragma unroll
    for (int r = 0; r < TOPK; r++) {
        if (r < k) {
            if (ti[r] == lane)      m0v = 1.0f;
            if (ti[r] == lane + 32) m1v = 1.0f;
        }
    }
    out[OFF_M + (size_t)n * NEXP + lane]      = m0v;
    out[OFF_M + (size_t)n * NEXP + lane + 32] = m1v;

    if (lane == 0) out[OFF_K + n] = (float)k;
}

// ---------------------------------------------------------------------------
extern "C" void kernel_launch(void* const* d_in, const int* in_sizes, int n_in,
                              void* d_out, int out_size) {
    const float* x  = (const float*)d_in[0];
    const float* W  = (const float*)d_in[1];
    const float* W1 = (const float*)d_in[2];
    const float* b1 = (const float*)d_in[3];
    const float* W2 = (const float*)d_in[4];
    const float* b2 = (const float*)d_in[5];
    float* out = (float*)d_out;

    static int smem_set = 0;
    if (!smem_set) {
        cudaFuncSetAttribute(gemm1_hmma, cudaFuncAttributeMaxDynamicSharedMemorySize, G1_SMEM);
        smem_set = 1;
    }

    // NOTE: launch order chosen so gemm1_hmma is launch index 3 (the one the
    // auto-ncu capture profiles).
    split_x<<<(int)(XPLANE / (256 * 4)), 256>>>(x);                   // 0
    split_w1t<<<dim3(DIM / 32, HID / 32), dim3(32, 8)>>>(W1);         // 1
    gemm_logits<<<NTOK / 64, 256>>>(x, W);                            // 2
    gemm1_hmma<<<dim3(HID / G1_BN, NTOK / G1_BM), 512, G1_SMEM>>>(b1); // 3 <- profiled
    reset_flags<<<1, 1>>>();                                          // 4
    predictor_k<<<NTOK, 256>>>(W2, b2);                               // 5
    repair_k<<<64, 256>>>(x, W1, b1, W2, b2);                         // 6
    finalize<<<NTOK / 8, 256>>>(out);                                 // 7
}

// round 8
// speedup vs baseline: 1.6694x; 1.6694x over previous
#include <cuda_runtime.h>
#include <cuda_bf16.h>
#include <math.h>
#include <stdint.h>

// Problem dims
#define NTOK 16384      // B*S
#define DIM  4096       // D (K of both GEMMs)
#define HID  2048       // H (N of GEMM1)
#define NEXP 64
#define TOPK 3

// Output layout (float32, concatenated flattened reference outputs)
#define OFF_W 0
#define OFF_I (NTOK * TOPK)
#define OFF_M (2 * NTOK * TOPK)
#define OFF_K (2 * NTOK * TOPK + NTOK * NEXP)

// Scratch (device globals)
#define XPLANE ((size_t)NTOK * DIM)
#define WPLANE ((size_t)HID * DIM)
#define FLAG_CAP 4096
#define RTOK 8
#define RCB  8   // column blocks of 256 cols (HID/256)
__device__ __align__(16) __nv_bfloat16 g_xs[XPLANE];    // 134 MB: x as bf16
__device__ __align__(16) __nv_bfloat16 g_w1t[WPLANE];   // 17 MB: W1^T bf16 [N][K]
__device__ float g_h[(size_t)NTOK * HID];               // 134 MB
__device__ float g_logits[(size_t)NTOK * NEXP];         // 4 MB
__device__ int   g_kdyn[NTOK];
__device__ int   g_nflag;
__device__ int   g_flaglist[FLAG_CAP];
__device__ double g_zpart[FLAG_CAP][RCB];

// ---------------------------------------------------------------------------
// PTX helpers (baseline sm_80+ ISA)
// ---------------------------------------------------------------------------
__device__ __forceinline__ uint32_t smem_u32(const void* p) {
    uint32_t a;
    asm("{ .reg .u64 t; cvta.to.shared.u64 t, %1; cvt.u32.u64 %0, t; }" : "=r"(a) : "l"(p));
    return a;
}
__device__ __forceinline__ void cp_async16(uint32_t dst, const void* src) {
    asm volatile("cp.async.cg.shared.global [%0], [%1], 16;" :: "r"(dst), "l"(src));
}
__device__ __forceinline__ void cp_commit() {
    asm volatile("cp.async.commit_group;");
}
template <int N>
__device__ __forceinline__ void cp_wait() {
    asm volatile("cp.async.wait_group %0;" :: "n"(N));
}
__device__ __forceinline__ void ldmatrix_x4(uint32_t& r0, uint32_t& r1, uint32_t& r2, uint32_t& r3,
                                            uint32_t addr) {
    asm volatile("ldmatrix.sync.aligned.m8n8.x4.shared.b16 {%0,%1,%2,%3}, [%4];"
                 : "=r"(r0), "=r"(r1), "=r"(r2), "=r"(r3) : "r"(addr));
}
__device__ __forceinline__ void mma_bf16(float* c, const uint32_t* a, const uint32_t* b) {
    asm volatile(
        "mma.sync.aligned.m16n8k16.row.col.f32.bf16.bf16.f32 "
        "{%0,%1,%2,%3}, {%4,%5,%6,%7}, {%8,%9}, {%0,%1,%2,%3};"
        : "+f"(c[0]), "+f"(c[1]), "+f"(c[2]), "+f"(c[3])
        : "r"(a[0]), "r"(a[1]), "r"(a[2]), "r"(a[3]), "r"(b[0]), "r"(b[1]));
}

// ---------------------------------------------------------------------------
// Conversion kernels (single bf16 plane)
// ---------------------------------------------------------------------------
__global__ __launch_bounds__(256) void split_x(const float* __restrict__ x) {
    size_t i = ((size_t)blockIdx.x * 256 + threadIdx.x) * 4;
    float4 v = *(const float4*)(x + i);
    ushort4 p;
    p.x = __bfloat16_as_ushort(__float2bfloat16_rn(v.x));
    p.y = __bfloat16_as_ushort(__float2bfloat16_rn(v.y));
    p.z = __bfloat16_as_ushort(__float2bfloat16_rn(v.z));
    p.w = __bfloat16_as_ushort(__float2bfloat16_rn(v.w));
    *(ushort4*)(g_xs + i) = p;
}

// W1 [K][N] fp32 -> W1^T [N][K] bf16 (tiled transpose)
__global__ __launch_bounds__(256) void split_w1t(const float* __restrict__ W1) {
    __shared__ float t[32][33];
    const int k0 = blockIdx.x * 32;
    const int n0 = blockIdx.y * 32;
    const int tx = threadIdx.x;
    const int ty = threadIdx.y;
    #pragma unroll
    for (int j = 0; j < 4; j++)
        t[ty + 8 * j][tx] = W1[(size_t)(k0 + ty + 8 * j) * HID + n0 + tx];
    __syncthreads();
    #pragma unroll
    for (int j = 0; j < 4; j++)
        g_w1t[(size_t)(n0 + ty + 8 * j) * DIM + k0 + tx] =
            __float2bfloat16_rn(t[tx][ty + 8 * j]);
}

// ---------------------------------------------------------------------------
// GEMM1: single-pass bf16 HMMA. h = relu(x_bf @ W1_bf + b1).
// CTA 128x128, BK=32, 256 threads, 8 warps (2Mx4N), warp tile 64x32.
// 3-stage cp.async pipeline, SMEM 60KB -> 2 CTAs/SM (16 warps).
// Accuracy handled downstream by flag+repair on dynamic_k.
// ---------------------------------------------------------------------------
#define G1_BM 128
#define G1_BN 128
#define G1_BK 32
#define PITCH 40                          // bf16 per smem row (80B, ldmatrix conflict-free)
#define TILE_B (128 * PITCH * 2)          // 10240 bytes
#define STAGE_B (2 * TILE_B)              // A + B = 20480
#define NSTAGE 3
#define G1_SMEM (NSTAGE * STAGE_B)        // 61440
#define G1_NIT (DIM / G1_BK)              // 128

__global__ __launch_bounds__(256) void gemm1_hmma(const float* __restrict__ bias) {
    extern __shared__ char smem[];
    const uint32_t sbase = smem_u32(smem);

    const int tid  = threadIdx.x;
    const int warp = tid >> 5;
    const int lane = tid & 31;
    const int m0 = blockIdx.y * G1_BM;
    const int n0 = blockIdx.x * G1_BN;

    const int wm = (warp >> 2) * 64;
    const int wn = (warp & 3) * 32;

    // global loads: tile lp (0=A,1=B), row lr, 4 x 16B per row
    const int lp = tid >> 7;
    const int lr = tid & 127;
    const __nv_bfloat16* lsrc =
        (lp == 0) ? (g_xs + (size_t)(m0 + lr) * DIM)
                  : (g_w1t + (size_t)(n0 + lr) * DIM);
    const uint32_t ldst_off = lp * TILE_B + lr * (PITCH * 2);

    float acc[4][4][4];
    #pragma unroll
    for (int i = 0; i < 4; i++)
        #pragma unroll
        for (int j = 0; j < 4; j++)
            #pragma unroll
            for (int q = 0; q < 4; q++) acc[i][j][q] = 0.f;

    auto load_stage = [&](int stage, int k0) {
        const uint32_t dst = sbase + stage * STAGE_B + ldst_off;
        const __nv_bfloat16* src = lsrc + k0;
        #pragma unroll
        for (int c = 0; c < 4; c++)
            cp_async16(dst + c * 16, src + c * 8);
        cp_commit();
    };

    load_stage(0, 0);
    load_stage(1, G1_BK);

    const int g = lane >> 3, r = lane & 7;

    for (int it = 0; it < G1_NIT; it++) {
        if (it + 2 < G1_NIT) {
            load_stage((it + 2) % NSTAGE, (it + 2) * G1_BK);
            cp_wait<2>();
        } else {
            cp_wait<0>();
        }
        __syncthreads();

        const uint32_t sb = sbase + (it % NSTAGE) * STAGE_B;
        const uint32_t At = sb;
        const uint32_t Bt = sb + TILE_B;

        #pragma unroll
        for (int s = 0; s < 2; s++) {       // two k16 steps
            uint32_t af[4][4];
            #pragma unroll
            for (int mb = 0; mb < 4; mb++) {
                const uint32_t off =
                    (uint32_t)(wm + mb * 16 + (g & 1) * 8 + r) * (PITCH * 2) + s * 32 + (g >> 1) * 16;
                ldmatrix_x4(af[mb][0], af[mb][1], af[mb][2], af[mb][3], At + off);
            }
            uint32_t bf[4][2];
            #pragma unroll
            for (int nbp = 0; nbp < 2; nbp++) {
                const uint32_t off =
                    (uint32_t)(wn + nbp * 16 + (g >> 1) * 8 + r) * (PITCH * 2) + s * 32 + (g & 1) * 16;
                uint32_t q0, q1, q2, q3;
                ldmatrix_x4(q0, q1, q2, q3, Bt + off);
                bf[nbp * 2][0] = q0; bf[nbp * 2][1] = q1;
                bf[nbp * 2 + 1][0] = q2; bf[nbp * 2 + 1][1] = q3;
            }
            #pragma unroll
            for (int mb = 0; mb < 4; mb++)
                #pragma unroll
                for (int nb = 0; nb < 4; nb++)
                    mma_bf16(acc[mb][nb], af[mb], bf[nb]);
        }
        __syncthreads();
    }

    // epilogue: bias + relu
    const int crow = lane >> 2;
    const int ccol = (lane & 3) * 2;
    #pragma unroll
    for (int mb = 0; mb < 4; mb++) {
        #pragma unroll
        for (int nb = 0; nb < 4; nb++) {
            const int col = n0 + wn + nb * 8 + ccol;
            const float b0 = bias[col], b1v = bias[col + 1];
            const int row0 = m0 + wm + mb * 16 + crow;
            float2 v0, v1;
            v0.x = fmaxf(acc[mb][nb][0] + b0, 0.f);
            v0.y = fmaxf(acc[mb][nb][1] + b1v, 0.f);
            v1.x = fmaxf(acc[mb][nb][2] + b0, 0.f);
            v1.y = fmaxf(acc[mb][nb][3] + b1v, 0.f);
            *(float2*)(g_h + (size_t)row0 * HID + col)       = v0;
            *(float2*)(g_h + (size_t)(row0 + 8) * HID + col) = v1;
        }
    }
}

// ---------------------------------------------------------------------------
// GEMM2 (high accuracy): g_logits = x @ W, fp32 partials + fp64 flush (proven)
// ---------------------------------------------------------------------------
__global__ __launch_bounds__(256) void gemm_logits(
    const float* __restrict__ A, const float* __restrict__ B
) {
    const int K = DIM;
    __shared__ float As_t[32][64];
    __shared__ float Bs[32][64];

    const int tid = threadIdx.x;
    const int m0 = blockIdx.x * 64;
    const int tg4 = (tid >> 4) * 4;
    const int eg4 = (tid & 15) * 4;

    double acc[4][4];
    #pragma unroll
    for (int i = 0; i < 4; i++)
        #pragma unroll
        for (int j = 0; j < 4; j++) acc[i][j] = 0.0;

    const int ar = tid >> 3;
    const int ac = (tid & 7) * 4;

    for (int k0 = 0; k0 < K; k0 += 32) {
        __syncthreads();
        #pragma unroll
        for (int it = 0; it < 2; it++) {
            const int r = it * 32 + ar;
            float4 av = *(const float4*)(A + (size_t)(m0 + r) * K + k0 + ac);
            As_t[ac + 0][r] = av.x;
            As_t[ac + 1][r] = av.y;
            As_t[ac + 2][r] = av.z;
            As_t[ac + 3][r] = av.w;
        }
        #pragma unroll
        for (int it = 0; it < 2; it++) {
            const int f = tid * 2 + it;
            const int kk = f >> 4;
            const int e4 = (f & 15) * 4;
            *(float4*)&Bs[kk][e4] = *(const float4*)(B + (size_t)(k0 + kk) * NEXP + e4);
        }
        __syncthreads();

        float part[4][4];
        #pragma unroll
        for (int i = 0; i < 4; i++)
            #pragma unroll
            for (int j = 0; j < 4; j++) part[i][j] = 0.f;

        #pragma unroll
        for (int kk = 0; kk < 32; kk++) {
            float4 a = *(const float4*)&As_t[kk][tg4];
            float4 b = *(const float4*)&Bs[kk][eg4];
            float av[4] = {a.x, a.y, a.z, a.w};
            float bv[4] = {b.x, b.y, b.z, b.w};
            #pragma unroll
            for (int i = 0; i < 4; i++)
                #pragma unroll
                for (int j = 0; j < 4; j++)
                    part[i][j] = fmaf(av[i], bv[j], part[i][j]);
            if ((kk & 7) == 7) {
                #pragma unroll
                for (int i = 0; i < 4; i++)
                    #pragma unroll
                    for (int j = 0; j < 4; j++) {
                        acc[i][j] += (double)part[i][j];
                        part[i][j] = 0.f;
                    }
            }
        }
    }

    #pragma unroll
    for (int i = 0; i < 4; i++) {
        const int row = m0 + tg4 + i;
        #pragma unroll
        for (int j = 0; j < 4; j++)
            g_logits[(size_t)row * NEXP + eg4 + j] = (float)acc[i][j];
    }
}

// ---------------------------------------------------------------------------
__global__ void reset_flags() { g_nflag = 0; }

// ---------------------------------------------------------------------------
// predictor: z = h@W2 + b2 -> dynamic_k; flag tokens near rounding boundaries.
// h is bf16-accurate => sigma(z error) ~1.1e-3; ZEPS = 0.012 ~ 11 sigma.
// ---------------------------------------------------------------------------
#define ZB 1.6094379124341003f
#define ZEPS 0.012f

__global__ __launch_bounds__(256) void predictor_k(
    const float* __restrict__ W2, const float* __restrict__ b2
) {
    __shared__ float red[256];
    const int n = blockIdx.x;
    const int tid = threadIdx.x;
    const float4* hp = (const float4*)(g_h + (size_t)n * HID);
    const float4* wp = (const float4*)W2;
    float acc = 0.f;
    #pragma unroll
    for (int j = tid; j < HID / 4; j += 256) {
        float4 h4 = hp[j];
        float4 w4 = wp[j];
        acc = fmaf(h4.x, w4.x, acc);
        acc = fmaf(h4.y, w4.y, acc);
        acc = fmaf(h4.z, w4.z, acc);
        acc = fmaf(h4.w, w4.w, acc);
    }
    red[tid] = acc;
    __syncthreads();
    for (int s = 128; s > 0; s >>= 1) {
        if (tid < s) red[tid] += red[tid + s];
        __syncthreads();
    }
    if (tid == 0) {
        float z = red[0] + b2[0];
        float score = 1.0f / (1.0f + expf(-z));
        float kf = rintf(score * 3.0f) + 1.0f;
        kf = fminf(fmaxf(kf, 1.0f), 3.0f);
        g_kdyn[n] = (int)kf;
        if (fabsf(z) < ZEPS || fabsf(z - ZB) < ZEPS || fabsf(z + ZB) < ZEPS) {
            int slot = atomicAdd(&g_nflag, 1);
            if (slot < FLAG_CAP) g_flaglist[slot] = n;
        }
    }
}

// ---------------------------------------------------------------------------
// repair phase A: batched accurate recompute of z-partials for flagged tokens.
// Work item = (group of 8 tokens) x (block of 256 HID cols). Each CTA computes
// a[tok, col] with fp32 64-chunk partials + fp64 flush, relu, dot with W2,
// writes deterministic per-colblock partial z. W1 read once per group.
// ---------------------------------------------------------------------------
#define RG_SMEM (RTOK * DIM * 4)   // 131072

__global__ __launch_bounds__(256) void repair_gemm(
    const float* __restrict__ x, const float* __restrict__ W1,
    const float* __restrict__ b1, const float* __restrict__ W2
) {
    extern __shared__ float xs[];   // [RTOK][DIM]
    __shared__ double zr[256];
    const int tid = threadIdx.x;
    const int cnt = min(g_nflag, FLAG_CAP);
    const int ngroups = (cnt + RTOK - 1) / RTOK;
    const int nwork = ngroups * RCB;

    for (int wk = blockIdx.x; wk < nwork; wk += gridDim.x) {
        const int grp = wk / RCB;
        const int cb = wk % RCB;
        const int g0 = grp * RTOK;
        const int nt = min(RTOK, cnt - g0);

        __syncthreads();
        for (int t = 0; t < nt; t++) {
            const int n = g_flaglist[g0 + t];
            const float4* src = (const float4*)(x + (size_t)n * DIM);
            float4* dst = (float4*)(xs + t * DIM);
            for (int j = tid; j < DIM / 4; j += 256) dst[j] = src[j];
        }
        __syncthreads();

        const int j = cb * 256 + tid;
        double aacc[RTOK];
        #pragma unroll
        for (int t = 0; t < RTOK; t++) aacc[t] = 0.0;

        for (int k0 = 0; k0 < DIM; k0 += 64) {
            float p[RTOK];
            #pragma unroll
            for (int t = 0; t < RTOK; t++) p[t] = 0.f;
            for (int k = 0; k < 64; k++) {
                const float w = W1[(size_t)(k0 + k) * HID + j];
                #pragma unroll
                for (int t = 0; t < RTOK; t++)
                    p[t] = fmaf(xs[t * DIM + k0 + k], w, p[t]);
            }
            #pragma unroll
            for (int t = 0; t < RTOK; t++) aacc[t] += (double)p[t];
        }

        const float w2j = W2[j];
        const float b1j = b1[j];
        for (int t = 0; t < nt; t++) {
            float h = fmaxf((float)(aacc[t] + (double)b1j), 0.f);
            zr[tid] = (double)h * (double)w2j;
            __syncthreads();
            for (int s = 128; s > 0; s >>= 1) {
                if (tid < s) zr[tid] += zr[tid + s];
                __syncthreads();
            }
            if (tid == 0) g_zpart[g0 + t][cb] = zr[0];
            __syncthreads();
        }
    }
}

// repair phase B: sum partials (fixed order), set dynamic_k for flagged tokens.
__global__ __launch_bounds__(256) void repair_finalize(const float* __restrict__ b2) {
    const int cnt = min(g_nflag, FLAG_CAP);
    const int i = blockIdx.x * 256 + threadIdx.x;
    if (i < cnt) {
        double z = (double)b2[0];
        #pragma unroll
        for (int c = 0; c < RCB; c++) z += g_zpart[i][c];
        float zf = (float)z;
        float score = 1.0f / (1.0f + expf(-zf));
        float kf = rintf(score * 3.0f) + 1.0f;
        kf = fminf(fmaxf(kf, 1.0f), 3.0f);
        g_kdyn[g_flaglist[i]] = (int)kf;
    }
}

// ---------------------------------------------------------------------------
// finalize: softmax/top-3 (rounded probs, lower-index ties)/mask/renorm
// ---------------------------------------------------------------------------
__global__ __launch_bounds__(256) void finalize(float* __restrict__ out) {
    const int warp = threadIdx.x >> 5;
    const int lane = threadIdx.x & 31;
    const int n = blockIdx.x * 8 + warp;

    const float* lp = g_logits + (size_t)n * NEXP;
    float l0 = lp[lane];
    float l1 = lp[lane + 32];

    float m = fmaxf(l0, l1);
    #pragma unroll
    for (int o = 16; o > 0; o >>= 1) m = fmaxf(m, __shfl_xor_sync(0xFFFFFFFFu, m, o));
    float e0 = expf(l0 - m);
    float e1 = expf(l1 - m);
    float s = e0 + e1;
    #pragma unroll
    for (int o = 16; o > 0; o >>= 1) s += __shfl_xor_sync(0xFFFFFFFFu, s, o);

    float p0 = e0 / s;
    float p1 = e1 / s;

    float c0 = p0, c1 = p1;
    float tv[TOPK];
    int   ti[TOPK];
    #pragma unroll
    for (int r = 0; r < TOPK; r++) {
        float v;
        int idx;
        if (c1 > c0) { v = c1; idx = lane + 32; }
        else         { v = c0; idx = lane; }
        #pragma unroll
        for (int o = 16; o > 0; o >>= 1) {
            float ov = __shfl_xor_sync(0xFFFFFFFFu, v, o);
            int   oi = __shfl_xor_sync(0xFFFFFFFFu, idx, o);
            if (ov > v || (ov == v && oi < idx)) { v = ov; idx = oi; }
        }
        tv[r] = v;
        ti[r] = idx;
        if (idx == lane)      c0 = -1.0f;
        if (idx == lane + 32) c1 = -1.0f;
    }

    const int k = g_kdyn[n];

    float msum = 0.f;
    #pragma unroll
    for (int r = 0; r < TOPK; r++)
        if (r < k) msum += tv[r];
    const float denom = msum + 1e-8f;

    if (lane < TOPK) {
        float w = (lane < k ? tv[lane] : 0.f) / denom;
        out[OFF_W + (size_t)n * TOPK + lane] = w;
        out[OFF_I + (size_t)n * TOPK + lane] = (float)ti[lane];
    }

    float m0v = 0.f, m1v = 0.f;
    #pragma unroll
    for (int r = 0; r < TOPK; r++) {
        if (r < k) {
            if (ti[r] == lane)      m0v = 1.0f;
            if (ti[r] == lane + 32) m1v = 1.0f;
        }
    }
    out[OFF_M + (size_t)n * NEXP + lane]      = m0v;
    out[OFF_M + (size_t)n * NEXP + lane + 32] = m1v;

    if (lane == 0) out[OFF_K + n] = (float)k;
}

// ---------------------------------------------------------------------------
extern "C" void kernel_launch(void* const* d_in, const int* in_sizes, int n_in,
                              void* d_out, int out_size) {
    const float* x  = (const float*)d_in[0];
    const float* W  = (const float*)d_in[1];
    const float* W1 = (const float*)d_in[2];
    const float* b1 = (const float*)d_in[3];
    const float* W2 = (const float*)d_in[4];
    const float* b2 = (const float*)d_in[5];
    float* out = (float*)d_out;

    static int smem_set = 0;
    if (!smem_set) {
        cudaFuncSetAttribute(gemm1_hmma, cudaFuncAttributeMaxDynamicSharedMemorySize, G1_SMEM);
        cudaFuncSetAttribute(repair_gemm, cudaFuncAttributeMaxDynamicSharedMemorySize, RG_SMEM);
        smem_set = 1;
    }

    // gemm1_hmma kept at launch index 3 (the auto-ncu capture target).
    split_x<<<(int)(XPLANE / (256 * 4)), 256>>>(x);                       // 0
    split_w1t<<<dim3(DIM / 32, HID / 32), dim3(32, 8)>>>(W1);             // 1
    gemm_logits<<<NTOK / 64, 256>>>(x, W);                                // 2
    gemm1_hmma<<<dim3(HID / G1_BN, NTOK / G1_BM), 256, G1_SMEM>>>(b1);    // 3 <- profiled
    reset_flags<<<1, 1>>>();                                              // 4
    predictor_k<<<NTOK, 256>>>(W2, b2);                                   // 5
    repair_gemm<<<256, 256, RG_SMEM>>>(x, W1, b1, W2);                    // 6
    repair_finalize<<<FLAG_CAP / 256, 256>>>(b2);                         // 7
    finalize<<<NTOK / 8, 256>>>(out);                                     // 8
}

// round 9
// speedup vs baseline: 1.8537x; 1.1104x over previous
#include <cuda_runtime.h>
#include <cuda_bf16.h>
#include <math.h>
#include <stdint.h>

// Problem dims
#define NTOK 16384      // B*S
#define DIM  4096       // D (K of both GEMMs)
#define HID  2048       // H (N of GEMM1)
#define NEXP 64
#define TOPK 3

// Output layout (float32, concatenated flattened reference outputs)
#define OFF_W 0
#define OFF_I (NTOK * TOPK)
#define OFF_M (2 * NTOK * TOPK)
#define OFF_K (2 * NTOK * TOPK + NTOK * NEXP)

// Scratch (device globals)
#define XPLANE ((size_t)NTOK * DIM)
#define WPLANE ((size_t)HID * DIM)
#define FLAG_CAP 4096
#define RTOK 8
#define RCB  8   // column blocks of 256 cols (HID/256)
__device__ __align__(16) __nv_bfloat16 g_xs[XPLANE];    // 134 MB: x as bf16
__device__ __align__(16) __nv_bfloat16 g_w1t[WPLANE];   // 17 MB: W1^T bf16 [N][K]
__device__ float g_h[(size_t)NTOK * HID];               // 134 MB
__device__ float g_logits[(size_t)NTOK * NEXP];         // 4 MB
__device__ int   g_kdyn[NTOK];
__device__ int   g_nflag;
__device__ int   g_flaglist[FLAG_CAP];
__device__ double g_zpart[FLAG_CAP][RCB];

// ---------------------------------------------------------------------------
// PTX helpers (baseline sm_80+ ISA)
// ---------------------------------------------------------------------------
__device__ __forceinline__ uint32_t smem_u32(const void* p) {
    uint32_t a;
    asm("{ .reg .u64 t; cvta.to.shared.u64 t, %1; cvt.u32.u64 %0, t; }" : "=r"(a) : "l"(p));
    return a;
}
__device__ __forceinline__ void cp_async16(uint32_t dst, const void* src) {
    asm volatile("cp.async.cg.shared.global [%0], [%1], 16;" :: "r"(dst), "l"(src));
}
__device__ __forceinline__ void cp_commit() {
    asm volatile("cp.async.commit_group;");
}
template <int N>
__device__ __forceinline__ void cp_wait() {
    asm volatile("cp.async.wait_group %0;" :: "n"(N));
}
__device__ __forceinline__ void ldmatrix_x4(uint32_t& r0, uint32_t& r1, uint32_t& r2, uint32_t& r3,
                                            uint32_t addr) {
    asm volatile("ldmatrix.sync.aligned.m8n8.x4.shared.b16 {%0,%1,%2,%3}, [%4];"
                 : "=r"(r0), "=r"(r1), "=r"(r2), "=r"(r3) : "r"(addr));
}
__device__ __forceinline__ void mma_bf16(float* c, const uint32_t* a, const uint32_t* b) {
    asm volatile(
        "mma.sync.aligned.m16n8k16.row.col.f32.bf16.bf16.f32 "
        "{%0,%1,%2,%3}, {%4,%5,%6,%7}, {%8,%9}, {%0,%1,%2,%3};"
        : "+f"(c[0]), "+f"(c[1]), "+f"(c[2]), "+f"(c[3])
        : "r"(a[0]), "r"(a[1]), "r"(a[2]), "r"(a[3]), "r"(b[0]), "r"(b[1]));
}

// ---------------------------------------------------------------------------
// Conversion kernels (single bf16 plane)
// ---------------------------------------------------------------------------
__global__ __launch_bounds__(256) void split_x(const float* __restrict__ x) {
    size_t i = ((size_t)blockIdx.x * 256 + threadIdx.x) * 4;
    float4 v = *(const float4*)(x + i);
    ushort4 p;
    p.x = __bfloat16_as_ushort(__float2bfloat16_rn(v.x));
    p.y = __bfloat16_as_ushort(__float2bfloat16_rn(v.y));
    p.z = __bfloat16_as_ushort(__float2bfloat16_rn(v.z));
    p.w = __bfloat16_as_ushort(__float2bfloat16_rn(v.w));
    *(ushort4*)(g_xs + i) = p;
}

// W1 [K][N] fp32 -> W1^T [N][K] bf16 (tiled transpose)
__global__ __launch_bounds__(256) void split_w1t(const float* __restrict__ W1) {
    __shared__ float t[32][33];
    const int k0 = blockIdx.x * 32;
    const int n0 = blockIdx.y * 32;
    const int tx = threadIdx.x;
    const int ty = threadIdx.y;
    #pragma unroll
    for (int j = 0; j < 4; j++)
        t[ty + 8 * j][tx] = W1[(size_t)(k0 + ty + 8 * j) * HID + n0 + tx];
    __syncthreads();
    #pragma unroll
    for (int j = 0; j < 4; j++)
        g_w1t[(size_t)(n0 + ty + 8 * j) * DIM + k0 + tx] =
            __float2bfloat16_rn(t[tx][ty + 8 * j]);
}

// ---------------------------------------------------------------------------
// GEMM1: single-pass bf16 HMMA. h = relu(x_bf @ W1_bf + b1).
// CTA 256x128, BK=32, 256 threads, 8 warps as 4Mx2N, warp tile 64x64.
// 4-stage cp.async pipeline (prefetch 3 ahead). PITCH=40 bf16 (80B rows):
// ldmatrix conflict-free. 32 independent MMAs per warp per k16 step.
// ---------------------------------------------------------------------------
#define G1_BM 256
#define G1_BN 128
#define G1_BK 32
#define PITCH 40                          // bf16 per smem row (80B)
#define STAGE_ROWS (G1_BM + G1_BN)        // 384 rows (A then B)
#define STAGE_B (STAGE_ROWS * PITCH * 2)  // 30720 bytes
#define NSTAGE 4
#define G1_SMEM (NSTAGE * STAGE_B)        // 122880
#define G1_NIT (DIM / G1_BK)              // 128

__global__ __launch_bounds__(256, 1) void gemm1_hmma(const float* __restrict__ bias) {
    extern __shared__ char smem[];
    const uint32_t sbase = smem_u32(smem);

    const int tid  = threadIdx.x;
    const int warp = tid >> 5;
    const int lane = tid & 31;
    const int m0 = blockIdx.y * G1_BM;
    const int n0 = blockIdx.x * G1_BN;

    const int wm = (warp >> 1) * 64;   // warp M offset (0..192)
    const int wn = (warp & 1) * 64;    // warp N offset (0 or 64)

    // global load mapping: 384 rows x 4 chunks(16B) = 1536 chunks; 6/thread.
    // chunk c: row = c*64 + (tid>>2), kchunk = tid&3.
    const __nv_bfloat16* lsrc[6];
    uint32_t ldst[6];
    #pragma unroll
    for (int c = 0; c < 6; c++) {
        const int row = c * 64 + (tid >> 2);
        const int kc = tid & 3;
        lsrc[c] = (row < G1_BM ? g_xs + (size_t)(m0 + row) * DIM
                               : g_w1t + (size_t)(n0 + row - G1_BM) * DIM) + kc * 8;
        ldst[c] = (uint32_t)row * (PITCH * 2) + kc * 16;
    }

    float acc[4][8][4];   // [mb][nb][frag] = 128 regs
    #pragma unroll
    for (int i = 0; i < 4; i++)
        #pragma unroll
        for (int j = 0; j < 8; j++)
            #pragma unroll
            for (int q = 0; q < 4; q++) acc[i][j][q] = 0.f;

    auto load_stage = [&](int stage, int k0) {
        const uint32_t dst = sbase + stage * STAGE_B;
        #pragma unroll
        for (int c = 0; c < 6; c++)
            cp_async16(dst + ldst[c], lsrc[c] + k0);
        cp_commit();
    };

    load_stage(0, 0);
    load_stage(1, G1_BK);
    load_stage(2, 2 * G1_BK);

    const int g = lane >> 3, r = lane & 7;

    for (int it = 0; it < G1_NIT; it++) {
        if (it + 3 < G1_NIT) {
            load_stage((it + 3) & (NSTAGE - 1), (it + 3) * G1_BK);
            cp_wait<3>();
        } else {
            cp_wait<0>();
        }
        __syncthreads();

        const uint32_t sb = sbase + (it & (NSTAGE - 1)) * STAGE_B;

        #pragma unroll
        for (int s = 0; s < 2; s++) {       // two k16 steps
            uint32_t af[4][4];
            #pragma unroll
            for (int mb = 0; mb < 4; mb++) {
                const uint32_t off =
                    (uint32_t)(wm + mb * 16 + (g & 1) * 8 + r) * (PITCH * 2) + s * 32 + (g >> 1) * 16;
                ldmatrix_x4(af[mb][0], af[mb][1], af[mb][2], af[mb][3], sb + off);
            }
            uint32_t bf[8][2];
            #pragma unroll
            for (int nbp = 0; nbp < 4; nbp++) {
                const uint32_t off =
                    (uint32_t)(G1_BM + wn + nbp * 16 + (g >> 1) * 8 + r) * (PITCH * 2) + s * 32 + (g & 1) * 16;
                uint32_t q0, q1, q2, q3;
                ldmatrix_x4(q0, q1, q2, q3, sb + off);
                bf[nbp * 2][0] = q0; bf[nbp * 2][1] = q1;
                bf[nbp * 2 + 1][0] = q2; bf[nbp * 2 + 1][1] = q3;
            }
            #pragma unroll
            for (int mb = 0; mb < 4; mb++)
                #pragma unroll
                for (int nb = 0; nb < 8; nb++)
                    mma_bf16(acc[mb][nb], af[mb], bf[nb]);
        }
        __syncthreads();
    }

    // epilogue: bias + relu
    const int crow = lane >> 2;
    const int ccol = (lane & 3) * 2;
    #pragma unroll
    for (int mb = 0; mb < 4; mb++) {
        #pragma unroll
        for (int nb = 0; nb < 8; nb++) {
            const int col = n0 + wn + nb * 8 + ccol;
            const float b0 = bias[col], b1v = bias[col + 1];
            const int row0 = m0 + wm + mb * 16 + crow;
            float2 v0, v1;
            v0.x = fmaxf(acc[mb][nb][0] + b0, 0.f);
            v0.y = fmaxf(acc[mb][nb][1] + b1v, 0.f);
            v1.x = fmaxf(acc[mb][nb][2] + b0, 0.f);
            v1.y = fmaxf(acc[mb][nb][3] + b1v, 0.f);
            *(float2*)(g_h + (size_t)row0 * HID + col)       = v0;
            *(float2*)(g_h + (size_t)(row0 + 8) * HID + col) = v1;
        }
    }
}

// ---------------------------------------------------------------------------
// GEMM2 (high accuracy): g_logits = x @ W, fp32 partials + fp64 flush (proven)
// ---------------------------------------------------------------------------
__global__ __launch_bounds__(256) void gemm_logits(
    const float* __restrict__ A, const float* __restrict__ B
) {
    const int K = DIM;
    __shared__ float As_t[32][64];
    __shared__ float Bs[32][64];

    const int tid = threadIdx.x;
    const int m0 = blockIdx.x * 64;
    const int tg4 = (tid >> 4) * 4;
    const int eg4 = (tid & 15) * 4;

    double acc[4][4];
    #pragma unroll
    for (int i = 0; i < 4; i++)
        #pragma unroll
        for (int j = 0; j < 4; j++) acc[i][j] = 0.0;

    const int ar = tid >> 3;
    const int ac = (tid & 7) * 4;

    for (int k0 = 0; k0 < K; k0 += 32) {
        __syncthreads();
        #pragma unroll
        for (int it = 0; it < 2; it++) {
            const int r = it * 32 + ar;
            float4 av = *(const float4*)(A + (size_t)(m0 + r) * K + k0 + ac);
            As_t[ac + 0][r] = av.x;
            As_t[ac + 1][r] = av.y;
            As_t[ac + 2][r] = av.z;
            As_t[ac + 3][r] = av.w;
        }
        #pragma unroll
        for (int it = 0; it < 2; it++) {
            const int f = tid * 2 + it;
            const int kk = f >> 4;
            const int e4 = (f & 15) * 4;
            *(float4*)&Bs[kk][e4] = *(const float4*)(B + (size_t)(k0 + kk) * NEXP + e4);
        }
        __syncthreads();

        float part[4][4];
        #pragma unroll
        for (int i = 0; i < 4; i++)
            #pragma unroll
            for (int j = 0; j < 4; j++) part[i][j] = 0.f;

        #pragma unroll
        for (int kk = 0; kk < 32; kk++) {
            float4 a = *(const float4*)&As_t[kk][tg4];
            float4 b = *(const float4*)&Bs[kk][eg4];
            float av[4] = {a.x, a.y, a.z, a.w};
            float bv[4] = {b.x, b.y, b.z, b.w};
            #pragma unroll
            for (int i = 0; i < 4; i++)
                #pragma unroll
                for (int j = 0; j < 4; j++)
                    part[i][j] = fmaf(av[i], bv[j], part[i][j]);
            if ((kk & 7) == 7) {
                #pragma unroll
                for (int i = 0; i < 4; i++)
                    #pragma unroll
                    for (int j = 0; j < 4; j++) {
                        acc[i][j] += (double)part[i][j];
                        part[i][j] = 0.f;
                    }
            }
        }
    }

    #pragma unroll
    for (int i = 0; i < 4; i++) {
        const int row = m0 + tg4 + i;
        #pragma unroll
        for (int j = 0; j < 4; j++)
            g_logits[(size_t)row * NEXP + eg4 + j] = (float)acc[i][j];
    }
}

// ---------------------------------------------------------------------------
__global__ void reset_flags() { g_nflag = 0; }

// ---------------------------------------------------------------------------
// predictor: z = h@W2 + b2 -> dynamic_k; flag tokens near rounding boundaries.
// h is bf16-accurate => sigma(z error) ~1.1e-3; ZEPS = 0.012 ~ 11 sigma.
// ---------------------------------------------------------------------------
#define ZB 1.6094379124341003f
#define ZEPS 0.012f

__global__ __launch_bounds__(256) void predictor_k(
    const float* __restrict__ W2, const float* __restrict__ b2
) {
    __shared__ float red[256];
    const int n = blockIdx.x;
    const int tid = threadIdx.x;
    const float4* hp = (const float4*)(g_h + (size_t)n * HID);
    const float4* wp = (const float4*)W2;
    float acc = 0.f;
    #pragma unroll
    for (int j = tid; j < HID / 4; j += 256) {
        float4 h4 = hp[j];
        float4 w4 = wp[j];
        acc = fmaf(h4.x, w4.x, acc);
        acc = fmaf(h4.y, w4.y, acc);
        acc = fmaf(h4.z, w4.z, acc);
        acc = fmaf(h4.w, w4.w, acc);
    }
    red[tid] = acc;
    __syncthreads();
    for (int s = 128; s > 0; s >>= 1) {
        if (tid < s) red[tid] += red[tid + s];
        __syncthreads();
    }
    if (tid == 0) {
        float z = red[0] + b2[0];
        float score = 1.0f / (1.0f + expf(-z));
        float kf = rintf(score * 3.0f) + 1.0f;
        kf = fminf(fmaxf(kf, 1.0f), 3.0f);
        g_kdyn[n] = (int)kf;
        if (fabsf(z) < ZEPS || fabsf(z - ZB) < ZEPS || fabsf(z + ZB) < ZEPS) {
            int slot = atomicAdd(&g_nflag, 1);
            if (slot < FLAG_CAP) g_flaglist[slot] = n;
        }
    }
}

// ---------------------------------------------------------------------------
// repair phase A: batched accurate recompute of z-partials for flagged tokens.
// ---------------------------------------------------------------------------
#define RG_SMEM (RTOK * DIM * 4)   // 131072

__global__ __launch_bounds__(256) void repair_gemm(
    const float* __restrict__ x, const float* __restrict__ W1,
    const float* __restrict__ b1, const float* __restrict__ W2
) {
    extern __shared__ float xs[];   // [RTOK][DIM]
    __shared__ double zr[256];
    const int tid = threadIdx.x;
    const int cnt = min(g_nflag, FLAG_CAP);
    const int ngroups = (cnt + RTOK - 1) / RTOK;
    const int nwork = ngroups * RCB;

    for (int wk = blockIdx.x; wk < nwork; wk += gridDim.x) {
        const int grp = wk / RCB;
        const int cb = wk % RCB;
        const int g0 = grp * RTOK;
        const int nt = min(RTOK, cnt - g0);

        __syncthreads();
        for (int t = 0; t < nt; t++) {
            const int n = g_flaglist[g0 + t];
            const float4* src = (const float4*)(x + (size_t)n * DIM);
            float4* dst = (float4*)(xs + t * DIM);
            for (int j = tid; j < DIM / 4; j += 256) dst[j] = src[j];
        }
        __syncthreads();

        const int j = cb * 256 + tid;
        double aacc[RTOK];
        #pragma unroll
        for (int t = 0; t < RTOK; t++) aacc[t] = 0.0;

        for (int k0 = 0; k0 < DIM; k0 += 64) {
            float p[RTOK];
            #pragma unroll
            for (int t = 0; t < RTOK; t++) p[t] = 0.f;
            for (int k = 0; k < 64; k++) {
                const float w = W1[(size_t)(k0 + k) * HID + j];
                #pragma unroll
                for (int t = 0; t < RTOK; t++)
                    p[t] = fmaf(xs[t * DIM + k0 + k], w, p[t]);
            }
            #pragma unroll
            for (int t = 0; t < RTOK; t++) aacc[t] += (double)p[t];
        }

        const float w2j = W2[j];
        const float b1j = b1[j];
        for (int t = 0; t < nt; t++) {
            float h = fmaxf((float)(aacc[t] + (double)b1j), 0.f);
            zr[tid] = (double)h * (double)w2j;
            __syncthreads();
            for (int s = 128; s > 0; s >>= 1) {
                if (tid < s) zr[tid] += zr[tid + s];
                __syncthreads();
            }
            if (tid == 0) g_zpart[g0 + t][cb] = zr[0];
            __syncthreads();
        }
    }
}

// repair phase B: sum partials (fixed order), set dynamic_k for flagged tokens.
__global__ __launch_bounds__(256) void repair_finalize(const float* __restrict__ b2) {
    const int cnt = min(g_nflag, FLAG_CAP);
    const int i = blockIdx.x * 256 + threadIdx.x;
    if (i < cnt) {
        double z = (double)b2[0];
        #pragma unroll
        for (int c = 0; c < RCB; c++) z += g_zpart[i][c];
        float zf = (float)z;
        float score = 1.0f / (1.0f + expf(-zf));
        float kf = rintf(score * 3.0f) + 1.0f;
        kf = fminf(fmaxf(kf, 1.0f), 3.0f);
        g_kdyn[g_flaglist[i]] = (int)kf;
    }
}

// ---------------------------------------------------------------------------
// finalize: softmax/top-3 (rounded probs, lower-index ties)/mask/renorm
// ---------------------------------------------------------------------------
__global__ __launch_bounds__(256) void finalize(float* __restrict__ out) {
    const int warp = threadIdx.x >> 5;
    const int lane = threadIdx.x & 31;
    const int n = blockIdx.x * 8 + warp;

    const float* lp = g_logits + (size_t)n * NEXP;
    float l0 = lp[lane];
    float l1 = lp[lane + 32];

    float m = fmaxf(l0, l1);
    #pragma unroll
    for (int o = 16; o > 0; o >>= 1) m = fmaxf(m, __shfl_xor_sync(0xFFFFFFFFu, m, o));
    float e0 = expf(l0 - m);
    float e1 = expf(l1 - m);
    float s = e0 + e1;
    #pragma unroll
    for (int o = 16; o > 0; o >>= 1) s += __shfl_xor_sync(0xFFFFFFFFu, s, o);

    float p0 = e0 / s;
    float p1 = e1 / s;

    float c0 = p0, c1 = p1;
    float tv[TOPK];
    int   ti[TOPK];
    #pragma unroll
    for (int r = 0; r < TOPK; r++) {
        float v;
        int idx;
        if (c1 > c0) { v = c1; idx = lane + 32; }
        else         { v = c0; idx = lane; }
        #pragma unroll
        for (int o = 16; o > 0; o >>= 1) {
            float ov = __shfl_xor_sync(0xFFFFFFFFu, v, o);
            int   oi = __shfl_xor_sync(0xFFFFFFFFu, idx, o);
            if (ov > v || (ov == v && oi < idx)) { v = ov; idx = oi; }
        }
        tv[r] = v;
        ti[r] = idx;
        if (idx == lane)      c0 = -1.0f;
        if (idx == lane + 32) c1 = -1.0f;
    }

    const int k = g_kdyn[n];

    float msum = 0.f;
    #pragma unroll
    for (int r = 0; r < TOPK; r++)
        if (r < k) msum += tv[r];
    const float denom = msum + 1e-8f;

    if (lane < TOPK) {
        float w = (lane < k ? tv[lane] : 0.f) / denom;
        out[OFF_W + (size_t)n * TOPK + lane] = w;
        out[OFF_I + (size_t)n * TOPK + lane] = (float)ti[lane];
    }

    float m0v = 0.f, m1v = 0.f;
    #pragma unroll
    for (int r = 0; r < TOPK; r++) {
        if (r < k) {
            if (ti[r] == lane)      m0v = 1.0f;
            if (ti[r] == lane + 32) m1v = 1.0f;
        }
    }
    out[OFF_M + (size_t)n * NEXP + lane]      = m0v;
    out[OFF_M + (size_t)n * NEXP + lane + 32] = m1v;

    if (lane == 0) out[OFF_K + n] = (float)k;
}

// ---------------------------------------------------------------------------
extern "C" void kernel_launch(void* const* d_in, const int* in_sizes, int n_in,
                              void* d_out, int out_size) {
    const float* x  = (const float*)d_in[0];
    const float* W  = (const float*)d_in[1];
    const float* W1 = (const float*)d_in[2];
    const float* b1 = (const float*)d_in[3];
    const float* W2 = (const float*)d_in[4];
    const float* b2 = (const float*)d_in[5];
    float* out = (float*)d_out;

    static int smem_set = 0;
    if (!smem_set) {
        cudaFuncSetAttribute(gemm1_hmma, cudaFuncAttributeMaxDynamicSharedMemorySize, G1_SMEM);
        cudaFuncSetAttribute(repair_gemm, cudaFuncAttributeMaxDynamicSharedMemorySize, RG_SMEM);
        smem_set = 1;
    }

    // gemm1_hmma kept at launch index 3 (the auto-ncu capture target).
    split_x<<<(int)(XPLANE / (256 * 4)), 256>>>(x);                       // 0
    split_w1t<<<dim3(DIM / 32, HID / 32), dim3(32, 8)>>>(W1);             // 1
    gemm_logits<<<NTOK / 64, 256>>>(x, W);                                // 2
    gemm1_hmma<<<dim3(HID / G1_BN, NTOK / G1_BM), 256, G1_SMEM>>>(b1);    // 3 <- profiled
    reset_flags<<<1, 1>>>();                                              // 4
    predictor_k<<<NTOK, 256>>>(W2, b2);                                   // 5
    repair_gemm<<<256, 256, RG_SMEM>>>(x, W1, b1, W2);                    // 6
    repair_finalize<<<FLAG_CAP / 256, 256>>>(b2);                         // 7
    finalize<<<NTOK / 8, 256>>>(out);                                     // 8
}

// round 10
// speedup vs baseline: 3.3740x; 1.8201x over previous
#include <cuda_runtime.h>
#include <cuda_bf16.h>
#include <math.h>
#include <stdint.h>

// Problem dims
#define NTOK 16384      // B*S
#define DIM  4096       // D (K of both GEMMs)
#define HID  2048       // H (N of GEMM1)
#define NEXP 64
#define TOPK 3

// Output layout (float32, concatenated flattened reference outputs)
#define OFF_W 0
#define OFF_I (NTOK * TOPK)
#define OFF_M (2 * NTOK * TOPK)
#define OFF_K (2 * NTOK * TOPK + NTOK * NEXP)

// Scratch (device globals)
#define XPLANE ((size_t)NTOK * DIM)
#define WPLANE ((size_t)HID * DIM)
#define FLAG_CAP 4096
#define RTOK 8
#define RCB  8   // column blocks of 256 cols (HID/256)
__device__ __align__(16) __nv_bfloat16 g_xs[XPLANE];    // 134 MB: x as bf16
__device__ __align__(16) __nv_bfloat16 g_w1t[WPLANE];   // 17 MB: W1^T bf16 [N][K]
__device__ float g_h[(size_t)NTOK * HID];               // 134 MB
__device__ float g_logits[(size_t)NTOK * NEXP];         // 4 MB
__device__ int   g_kdyn[NTOK];
__device__ int   g_nflag;
__device__ int   g_flaglist[FLAG_CAP];
__device__ double g_zpart[FLAG_CAP][RCB];

// ---------------------------------------------------------------------------
// PTX helpers (baseline sm_80+ ISA)
// ---------------------------------------------------------------------------
__device__ __forceinline__ uint32_t smem_u32(const void* p) {
    uint32_t a;
    asm("{ .reg .u64 t; cvta.to.shared.u64 t, %1; cvt.u32.u64 %0, t; }" : "=r"(a) : "l"(p));
    return a;
}
__device__ __forceinline__ void cp_async16(uint32_t dst, const void* src) {
    asm volatile("cp.async.cg.shared.global [%0], [%1], 16;" :: "r"(dst), "l"(src));
}
__device__ __forceinline__ void cp_commit() {
    asm volatile("cp.async.commit_group;");
}
template <int N>
__device__ __forceinline__ void cp_wait() {
    asm volatile("cp.async.wait_group %0;" :: "n"(N));
}
__device__ __forceinline__ void ldmatrix_x4(uint32_t& r0, uint32_t& r1, uint32_t& r2, uint32_t& r3,
                                            uint32_t addr) {
    asm volatile("ldmatrix.sync.aligned.m8n8.x4.shared.b16 {%0,%1,%2,%3}, [%4];"
                 : "=r"(r0), "=r"(r1), "=r"(r2), "=r"(r3) : "r"(addr));
}
__device__ __forceinline__ void mma_bf16(float* c, const uint32_t* a, const uint32_t* b) {
    asm volatile(
        "mma.sync.aligned.m16n8k16.row.col.f32.bf16.bf16.f32 "
        "{%0,%1,%2,%3}, {%4,%5,%6,%7}, {%8,%9}, {%0,%1,%2,%3};"
        : "+f"(c[0]), "+f"(c[1]), "+f"(c[2]), "+f"(c[3])
        : "r"(a[0]), "r"(a[1]), "r"(a[2]), "r"(a[3]), "r"(b[0]), "r"(b[1]));
}

// ---------------------------------------------------------------------------
// Conversion kernels (single bf16 plane)
// ---------------------------------------------------------------------------
__global__ __launch_bounds__(256) void split_x(const float* __restrict__ x) {
    size_t i = ((size_t)blockIdx.x * 256 + threadIdx.x) * 4;
    float4 v = *(const float4*)(x + i);
    ushort4 p;
    p.x = __bfloat16_as_ushort(__float2bfloat16_rn(v.x));
    p.y = __bfloat16_as_ushort(__float2bfloat16_rn(v.y));
    p.z = __bfloat16_as_ushort(__float2bfloat16_rn(v.z));
    p.w = __bfloat16_as_ushort(__float2bfloat16_rn(v.w));
    *(ushort4*)(g_xs + i) = p;
}

// W1 [K][N] fp32 -> W1^T [N][K] bf16 (tiled transpose)
__global__ __launch_bounds__(256) void split_w1t(const float* __restrict__ W1) {
    __shared__ float t[32][33];
    const int k0 = blockIdx.x * 32;
    const int n0 = blockIdx.y * 32;
    const int tx = threadIdx.x;
    const int ty = threadIdx.y;
    #pragma unroll
    for (int j = 0; j < 4; j++)
        t[ty + 8 * j][tx] = W1[(size_t)(k0 + ty + 8 * j) * HID + n0 + tx];
    __syncthreads();
    #pragma unroll
    for (int j = 0; j < 4; j++)
        g_w1t[(size_t)(n0 + ty + 8 * j) * DIM + k0 + tx] =
            __float2bfloat16_rn(t[tx][ty + 8 * j]);
}

// ---------------------------------------------------------------------------
// GEMM1: single-pass bf16 HMMA. h = relu(x_bf @ W1_bf + b1).
// CTA 256x128, BK=32, 256 threads, 8 warps as 4Mx2N, warp tile 64x64.
// 4-stage cp.async pipeline. (Proven round 9: 912us.)
// ---------------------------------------------------------------------------
#define G1_BM 256
#define G1_BN 128
#define G1_BK 32
#define PITCH 40                          // bf16 per smem row (80B)
#define STAGE_ROWS (G1_BM + G1_BN)        // 384 rows (A then B)
#define STAGE_B (STAGE_ROWS * PITCH * 2)  // 30720 bytes
#define NSTAGE 4
#define G1_SMEM (NSTAGE * STAGE_B)        // 122880
#define G1_NIT (DIM / G1_BK)              // 128

__global__ __launch_bounds__(256, 1) void gemm1_hmma(const float* __restrict__ bias) {
    extern __shared__ char smem[];
    const uint32_t sbase = smem_u32(smem);

    const int tid  = threadIdx.x;
    const int warp = tid >> 5;
    const int lane = tid & 31;
    const int m0 = blockIdx.y * G1_BM;
    const int n0 = blockIdx.x * G1_BN;

    const int wm = (warp >> 1) * 64;
    const int wn = (warp & 1) * 64;

    const __nv_bfloat16* lsrc[6];
    uint32_t ldst[6];
    #pragma unroll
    for (int c = 0; c < 6; c++) {
        const int row = c * 64 + (tid >> 2);
        const int kc = tid & 3;
        lsrc[c] = (row < G1_BM ? g_xs + (size_t)(m0 + row) * DIM
                               : g_w1t + (size_t)(n0 + row - G1_BM) * DIM) + kc * 8;
        ldst[c] = (uint32_t)row * (PITCH * 2) + kc * 16;
    }

    float acc[4][8][4];
    #pragma unroll
    for (int i = 0; i < 4; i++)
        #pragma unroll
        for (int j = 0; j < 8; j++)
            #pragma unroll
            for (int q = 0; q < 4; q++) acc[i][j][q] = 0.f;

    auto load_stage = [&](int stage, int k0) {
        const uint32_t dst = sbase + stage * STAGE_B;
        #pragma unroll
        for (int c = 0; c < 6; c++)
            cp_async16(dst + ldst[c], lsrc[c] + k0);
        cp_commit();
    };

    load_stage(0, 0);
    load_stage(1, G1_BK);
    load_stage(2, 2 * G1_BK);

    const int g = lane >> 3, r = lane & 7;

    for (int it = 0; it < G1_NIT; it++) {
        if (it + 3 < G1_NIT) {
            load_stage((it + 3) & (NSTAGE - 1), (it + 3) * G1_BK);
            cp_wait<3>();
        } else {
            cp_wait<0>();
        }
        __syncthreads();

        const uint32_t sb = sbase + (it & (NSTAGE - 1)) * STAGE_B;

        #pragma unroll
        for (int s = 0; s < 2; s++) {
            uint32_t af[4][4];
            #pragma unroll
            for (int mb = 0; mb < 4; mb++) {
                const uint32_t off =
                    (uint32_t)(wm + mb * 16 + (g & 1) * 8 + r) * (PITCH * 2) + s * 32 + (g >> 1) * 16;
                ldmatrix_x4(af[mb][0], af[mb][1], af[mb][2], af[mb][3], sb + off);
            }
            uint32_t bf[8][2];
            #pragma unroll
            for (int nbp = 0; nbp < 4; nbp++) {
                const uint32_t off =
                    (uint32_t)(G1_BM + wn + nbp * 16 + (g >> 1) * 8 + r) * (PITCH * 2) + s * 32 + (g & 1) * 16;
                uint32_t q0, q1, q2, q3;
                ldmatrix_x4(q0, q1, q2, q3, sb + off);
                bf[nbp * 2][0] = q0; bf[nbp * 2][1] = q1;
                bf[nbp * 2 + 1][0] = q2; bf[nbp * 2 + 1][1] = q3;
            }
            #pragma unroll
            for (int mb = 0; mb < 4; mb++)
                #pragma unroll
                for (int nb = 0; nb < 8; nb++)
                    mma_bf16(acc[mb][nb], af[mb], bf[nb]);
        }
        __syncthreads();
    }

    const int crow = lane >> 2;
    const int ccol = (lane & 3) * 2;
    #pragma unroll
    for (int mb = 0; mb < 4; mb++) {
        #pragma unroll
        for (int nb = 0; nb < 8; nb++) {
            const int col = n0 + wn + nb * 8 + ccol;
            const float b0 = bias[col], b1v = bias[col + 1];
            const int row0 = m0 + wm + mb * 16 + crow;
            float2 v0, v1;
            v0.x = fmaxf(acc[mb][nb][0] + b0, 0.f);
            v0.y = fmaxf(acc[mb][nb][1] + b1v, 0.f);
            v1.x = fmaxf(acc[mb][nb][2] + b0, 0.f);
            v1.y = fmaxf(acc[mb][nb][3] + b1v, 0.f);
            *(float2*)(g_h + (size_t)row0 * HID + col)       = v0;
            *(float2*)(g_h + (size_t)(row0 + 8) * HID + col) = v1;
        }
    }
}

// ---------------------------------------------------------------------------
// GEMM2 (high accuracy, NO fp64): g_logits = x @ W.
// fp32 partials over 8-term chunks + Neumaier-compensated fp32 accumulation
// (TwoSum via __fadd_rn/__fsub_rn, immune to contraction). Final = s + c.
// Error ~eps*|logit| ~ 4e-7: same class as the proven fp64-flush version,
// but entirely on the FMA pipe (B300 fp64 vector is ~2-4 ops/cyc/SM).
// ---------------------------------------------------------------------------
__global__ __launch_bounds__(256) void gemm_logits(
    const float* __restrict__ A, const float* __restrict__ B
) {
    const int K = DIM;
    __shared__ float As_t[32][64];
    __shared__ float Bs[32][64];

    const int tid = threadIdx.x;
    const int m0 = blockIdx.x * 64;
    const int tg4 = (tid >> 4) * 4;
    const int eg4 = (tid & 15) * 4;

    float accs[4][4];   // compensated sum (high part)
    float accc[4][4];   // compensation (low part)
    #pragma unroll
    for (int i = 0; i < 4; i++)
        #pragma unroll
        for (int j = 0; j < 4; j++) { accs[i][j] = 0.f; accc[i][j] = 0.f; }

    const int ar = tid >> 3;
    const int ac = (tid & 7) * 4;

    for (int k0 = 0; k0 < K; k0 += 32) {
        __syncthreads();
        #pragma unroll
        for (int it = 0; it < 2; it++) {
            const int r = it * 32 + ar;
            float4 av = *(const float4*)(A + (size_t)(m0 + r) * K + k0 + ac);
            As_t[ac + 0][r] = av.x;
            As_t[ac + 1][r] = av.y;
            As_t[ac + 2][r] = av.z;
            As_t[ac + 3][r] = av.w;
        }
        #pragma unroll
        for (int it = 0; it < 2; it++) {
            const int f = tid * 2 + it;
            const int kk = f >> 4;
            const int e4 = (f & 15) * 4;
            *(float4*)&Bs[kk][e4] = *(const float4*)(B + (size_t)(k0 + kk) * NEXP + e4);
        }
        __syncthreads();

        float part[4][4];
        #pragma unroll
        for (int i = 0; i < 4; i++)
            #pragma unroll
            for (int j = 0; j < 4; j++) part[i][j] = 0.f;

        #pragma unroll
        for (int kk = 0; kk < 32; kk++) {
            float4 a = *(const float4*)&As_t[kk][tg4];
            float4 b = *(const float4*)&Bs[kk][eg4];
            float av[4] = {a.x, a.y, a.z, a.w};
            float bv[4] = {b.x, b.y, b.z, b.w};
            #pragma unroll
            for (int i = 0; i < 4; i++)
                #pragma unroll
                for (int j = 0; j < 4; j++)
                    part[i][j] = fmaf(av[i], bv[j], part[i][j]);
            if ((kk & 7) == 7) {
                // Neumaier compensated add: (accs, accc) += part
                #pragma unroll
                for (int i = 0; i < 4; i++)
                    #pragma unroll
                    for (int j = 0; j < 4; j++) {
                        const float p = part[i][j];
                        const float s0 = accs[i][j];
                        const float t = __fadd_rn(s0, p);
                        const float e = (fabsf(s0) >= fabsf(p))
                            ? __fadd_rn(__fsub_rn(s0, t), p)
                            : __fadd_rn(__fsub_rn(p, t), s0);
                        accc[i][j] = __fadd_rn(accc[i][j], e);
                        accs[i][j] = t;
                        part[i][j] = 0.f;
                    }
            }
        }
    }

    #pragma unroll
    for (int i = 0; i < 4; i++) {
        const int row = m0 + tg4 + i;
        #pragma unroll
        for (int j = 0; j < 4; j++)
            g_logits[(size_t)row * NEXP + eg4 + j] = __fadd_rn(accs[i][j], accc[i][j]);
    }
}

// ---------------------------------------------------------------------------
__global__ void reset_flags() { g_nflag = 0; }

// ---------------------------------------------------------------------------
// predictor: z = h@W2 + b2 -> dynamic_k; flag tokens near rounding boundaries.
// ---------------------------------------------------------------------------
#define ZB 1.6094379124341003f
#define ZEPS 0.012f

__global__ __launch_bounds__(256) void predictor_k(
    const float* __restrict__ W2, const float* __restrict__ b2
) {
    __shared__ float red[256];
    const int n = blockIdx.x;
    const int tid = threadIdx.x;
    const float4* hp = (const float4*)(g_h + (size_t)n * HID);
    const float4* wp = (const float4*)W2;
    float acc = 0.f;
    #pragma unroll
    for (int j = tid; j < HID / 4; j += 256) {
        float4 h4 = hp[j];
        float4 w4 = wp[j];
        acc = fmaf(h4.x, w4.x, acc);
        acc = fmaf(h4.y, w4.y, acc);
        acc = fmaf(h4.z, w4.z, acc);
        acc = fmaf(h4.w, w4.w, acc);
    }
    red[tid] = acc;
    __syncthreads();
    for (int s = 128; s > 0; s >>= 1) {
        if (tid < s) red[tid] += red[tid + s];
        __syncthreads();
    }
    if (tid == 0) {
        float z = red[0] + b2[0];
        float score = 1.0f / (1.0f + expf(-z));
        float kf = rintf(score * 3.0f) + 1.0f;
        kf = fminf(fmaxf(kf, 1.0f), 3.0f);
        g_kdyn[n] = (int)kf;
        if (fabsf(z) < ZEPS || fabsf(z - ZB) < ZEPS || fabsf(z + ZB) < ZEPS) {
            int slot = atomicAdd(&g_nflag, 1);
            if (slot < FLAG_CAP) g_flaglist[slot] = n;
        }
    }
}

// ---------------------------------------------------------------------------
// repair phase A: batched accurate recompute of z-partials for flagged tokens.
// (fp64 kept here: ~0.1% of tokens, off the critical path.)
// ---------------------------------------------------------------------------
#define RG_SMEM (RTOK * DIM * 4)   // 131072

__global__ __launch_bounds__(256) void repair_gemm(
    const float* __restrict__ x, const float* __restrict__ W1,
    const float* __restrict__ b1, const float* __restrict__ W2
) {
    extern __shared__ float xs[];   // [RTOK][DIM]
    __shared__ double zr[256];
    const int tid = threadIdx.x;
    const int cnt = min(g_nflag, FLAG_CAP);
    const int ngroups = (cnt + RTOK - 1) / RTOK;
    const int nwork = ngroups * RCB;

    for (int wk = blockIdx.x; wk < nwork; wk += gridDim.x) {
        const int grp = wk / RCB;
        const int cb = wk % RCB;
        const int g0 = grp * RTOK;
        const int nt = min(RTOK, cnt - g0);

        __syncthreads();
        for (int t = 0; t < nt; t++) {
            const int n = g_flaglist[g0 + t];
            const float4* src = (const float4*)(x + (size_t)n * DIM);
            float4* dst = (float4*)(xs + t * DIM);
            for (int j = tid; j < DIM / 4; j += 256) dst[j] = src[j];
        }
        __syncthreads();

        const int j = cb * 256 + tid;
        double aacc[RTOK];
        #pragma unroll
        for (int t = 0; t < RTOK; t++) aacc[t] = 0.0;

        for (int k0 = 0; k0 < DIM; k0 += 64) {
            float p[RTOK];
            #pragma unroll
            for (int t = 0; t < RTOK; t++) p[t] = 0.f;
            for (int k = 0; k < 64; k++) {
                const float w = W1[(size_t)(k0 + k) * HID + j];
                #pragma unroll
                for (int t = 0; t < RTOK; t++)
                    p[t] = fmaf(xs[t * DIM + k0 + k], w, p[t]);
            }
            #pragma unroll
            for (int t = 0; t < RTOK; t++) aacc[t] += (double)p[t];
        }

        const float w2j = W2[j];
        const float b1j = b1[j];
        for (int t = 0; t < nt; t++) {
            float h = fmaxf((float)(aacc[t] + (double)b1j), 0.f);
            zr[tid] = (double)h * (double)w2j;
            __syncthreads();
            for (int s = 128; s > 0; s >>= 1) {
                if (tid < s) zr[tid] += zr[tid + s];
                __syncthreads();
            }
            if (tid == 0) g_zpart[g0 + t][cb] = zr[0];
            __syncthreads();
        }
    }
}

// repair phase B: sum partials (fixed order), set dynamic_k for flagged tokens.
__global__ __launch_bounds__(256) void repair_finalize(const float* __restrict__ b2) {
    const int cnt = min(g_nflag, FLAG_CAP);
    const int i = blockIdx.x * 256 + threadIdx.x;
    if (i < cnt) {
        double z = (double)b2[0];
        #pragma unroll
        for (int c = 0; c < RCB; c++) z += g_zpart[i][c];
        float zf = (float)z;
        float score = 1.0f / (1.0f + expf(-zf));
        float kf = rintf(score * 3.0f) + 1.0f;
        kf = fminf(fmaxf(kf, 1.0f), 3.0f);
        g_kdyn[g_flaglist[i]] = (int)kf;
    }
}

// ---------------------------------------------------------------------------
// finalize: softmax/top-3 (rounded probs, lower-index ties)/mask/renorm
// ---------------------------------------------------------------------------
__global__ __launch_bounds__(256) void finalize(float* __restrict__ out) {
    const int warp = threadIdx.x >> 5;
    const int lane = threadIdx.x & 31;
    const int n = blockIdx.x * 8 + warp;

    const float* lp = g_logits + (size_t)n * NEXP;
    float l0 = lp[lane];
    float l1 = lp[lane + 32];

    float m = fmaxf(l0, l1);
    #pragma unroll
    for (int o = 16; o > 0; o >>= 1) m = fmaxf(m, __shfl_xor_sync(0xFFFFFFFFu, m, o));
    float e0 = expf(l0 - m);
    float e1 = expf(l1 - m);
    float s = e0 + e1;
    #pragma unroll
    for (int o = 16; o > 0; o >>= 1) s += __shfl_xor_sync(0xFFFFFFFFu, s, o);

    float p0 = e0 / s;
    float p1 = e1 / s;

    float c0 = p0, c1 = p1;
    float tv[TOPK];
    int   ti[TOPK];
    #pragma unroll
    for (int r = 0; r < TOPK; r++) {
        float v;
        int idx;
        if (c1 > c0) { v = c1; idx = lane + 32; }
        else         { v = c0; idx = lane; }
        #pragma unroll
        for (int o = 16; o > 0; o >>= 1) {
            float ov = __shfl_xor_sync(0xFFFFFFFFu, v, o);
            int   oi = __shfl_xor_sync(0xFFFFFFFFu, idx, o);
            if (ov > v || (ov == v && oi < idx)) { v = ov; idx = oi; }
        }
        tv[r] = v;
        ti[r] = idx;
        if (idx == lane)      c0 = -1.0f;
        if (idx == lane + 32) c1 = -1.0f;
    }

    const int k = g_kdyn[n];

    float msum = 0.f;
    #pragma unroll
    for (int r = 0; r < TOPK; r++)
        if (r < k) msum += tv[r];
    const float denom = msum + 1e-8f;

    if (lane < TOPK) {
        float w = (lane < k ? tv[lane] : 0.f) / denom;
        out[OFF_W + (size_t)n * TOPK + lane] = w;
        out[OFF_I + (size_t)n * TOPK + lane] = (float)ti[lane];
    }

    float m0v = 0.f, m1v = 0.f;
    #pragma unroll
    for (int r = 0; r < TOPK; r++) {
        if (r < k) {
            if (ti[r] == lane)      m0v = 1.0f;
            if (ti[r] == lane + 32) m1v = 1.0f;
        }
    }
    out[OFF_M + (size_t)n * NEXP + lane]      = m0v;
    out[OFF_M + (size_t)n * NEXP + lane + 32] = m1v;

    if (lane == 0) out[OFF_K + n] = (float)k;
}

// ---------------------------------------------------------------------------
extern "C" void kernel_launch(void* const* d_in, const int* in_sizes, int n_in,
                              void* d_out, int out_size) {
    const float* x  = (const float*)d_in[0];
    const float* W  = (const float*)d_in[1];
    const float* W1 = (const float*)d_in[2];
    const float* b1 = (const float*)d_in[3];
    const float* W2 = (const float*)d_in[4];
    const float* b2 = (const float*)d_in[5];
    float* out = (float*)d_out;

    static int smem_set = 0;
    if (!smem_set) {
        cudaFuncSetAttribute(gemm1_hmma, cudaFuncAttributeMaxDynamicSharedMemorySize, G1_SMEM);
        cudaFuncSetAttribute(repair_gemm, cudaFuncAttributeMaxDynamicSharedMemorySize, RG_SMEM);
        smem_set = 1;
    }

    // gemm_logits placed at launch index 3 (the auto-ncu capture target)
    // to verify the fp64 -> compensated-fp32 fix directly.
    split_x<<<(int)(XPLANE / (256 * 4)), 256>>>(x);                       // 0
    split_w1t<<<dim3(DIM / 32, HID / 32), dim3(32, 8)>>>(W1);             // 1
    gemm1_hmma<<<dim3(HID / G1_BN, NTOK / G1_BM), 256, G1_SMEM>>>(b1);    // 2
    gemm_logits<<<NTOK / 64, 256>>>(x, W);                                // 3 <- profiled
    reset_flags<<<1, 1>>>();                                              // 4
    predictor_k<<<NTOK, 256>>>(W2, b2);                                   // 5
    repair_gemm<<<256, 256, RG_SMEM>>>(x, W1, b1, W2);                    // 6
    repair_finalize<<<FLAG_CAP / 256, 256>>>(b2);                         // 7
    finalize<<<NTOK / 8, 256>>>(out);                                     // 8
}